// round 9
// baseline (speedup 1.0000x reference)
#include <cuda_runtime.h>
#include <cuda_bf16.h>
#include <cstdint>

// out = norm @ ((norm^T @ x) @ W),  norm = x / max(||x_row||, 1e-12)
// y = sqrt(inv)*x  =>  G = y^T @ y (symmetric).
// int8 IMMA m16n8k32, base-253 2-digit quantization, 4 exact passes:
//   v = s*(253*c1 + c2), C = sa*sb*(64009*P11 + 253*(P12+P21) + P22)
// G's dominant diagonal is kept in fp32 and re-added to H after GEMM2.

#define NROWS 8192
#define DIM   1024
typedef signed char s8;

// ---------------- scratch (device globals; no allocation allowed) ----------
__device__ float g_inv[NROWS];
// amax slots: [0]=y, [1]=w, [2]=G_offdiag, [3]=H, [4]=norm
__device__ unsigned g_amax[5];
__device__ float g_diag[DIM];
__device__ s8 q_n1[NROWS * DIM], q_n2[NROWS * DIM];     // norm quant (row-major)
__device__ s8 q_y1[DIM * NROWS], q_y2[DIM * NROWS];     // y^T quant
__device__ s8 q_w1[DIM * DIM],   q_w2[DIM * DIM];       // W^T quant
__device__ s8 q_g1[DIM * DIM],   q_g2[DIM * DIM];       // G quant (diag zeroed)
__device__ s8 q_h1[DIM * DIM],   q_h2[DIM * DIM];       // H^T quant
__device__ float g_Gf[DIM * DIM], g_Hf[DIM * DIM];      // fp32 intermediates
__device__ float g_P[4 * DIM * DIM];                    // split-K partials

__constant__ int2 c_tri[36] = {
    {0,0},{1,0},{1,1},{2,0},{2,1},{2,2},{3,0},{3,1},{3,2},{3,3},
    {4,0},{4,1},{4,2},{4,3},{4,4},{5,0},{5,1},{5,2},{5,3},{5,4},
    {5,5},{6,0},{6,1},{6,2},{6,3},{6,4},{6,5},{6,6},{7,0},{7,1},
    {7,2},{7,3},{7,4},{7,5},{7,6},{7,7}
};

// ---------------- PTX helpers ----------------------------------------------
__device__ __forceinline__ uint32_t smem_u32(const void* p) {
    uint32_t a;
    asm("{ .reg .u64 t; cvta.to.shared.u64 t, %1; cvt.u32.u64 %0, t; }" : "=r"(a) : "l"(p));
    return a;
}

#define CP16(saddr, gptr) \
    asm volatile("cp.async.cg.shared.global [%0], [%1], 16;" :: "r"(saddr), "l"(gptr))
#define CP_COMMIT() asm volatile("cp.async.commit_group;" ::: "memory")
#define CP_WAIT(n)  asm volatile("cp.async.wait_group %0;" :: "n"(n) : "memory")

#define LDSM4(r, addr) \
    asm volatile("ldmatrix.sync.aligned.m8n8.x4.shared.b16 {%0,%1,%2,%3}, [%4];" \
        : "=r"((r)[0]), "=r"((r)[1]), "=r"((r)[2]), "=r"((r)[3]) : "r"(addr))

#define IMMA(c, a, b) \
    asm volatile("mma.sync.aligned.m16n8k32.row.col.s32.s8.s8.s32 " \
        "{%0,%1,%2,%3}, {%4,%5,%6,%7}, {%8,%9}, {%0,%1,%2,%3};" \
        : "+r"((c)[0]), "+r"((c)[1]), "+r"((c)[2]), "+r"((c)[3]) \
        : "r"((a)[0]), "r"((a)[1]), "r"((a)[2]), "r"((a)[3]), "r"((b)[0]), "r"((b)[1]))

// ---------------- quantization ----------------------------------------------
// t = v*32000/amax; v = (amax/32000)*(253*c1 + c2) + eps, |eps| <= 0.5 ulp
__device__ __forceinline__ void quant2(float v, float k, s8& c1, s8& c2) {
    float t = v * k;
    float f1 = rintf(t * (1.0f / 253.0f));
    float f2 = rintf(fmaf(-253.0f, f1, t));
    c1 = (s8)(int)f1;
    c2 = (s8)(int)f2;
}

__device__ __forceinline__ void atomic_fmax(unsigned* addr, float v) {
    atomicMax(addr, __float_as_uint(v));
}

// ---------------- small kernels --------------------------------------------
__global__ void init_amax() {
    if (threadIdx.x < 5) g_amax[threadIdx.x] = 0u;
}

__global__ void rownorm_inv(const float* __restrict__ x, float* __restrict__ inv) {
    const int row = blockIdx.x;
    float4 v = reinterpret_cast<const float4*>(x + (size_t)row * DIM)[threadIdx.x];
    float s = v.x * v.x + v.y * v.y + v.z * v.z + v.w * v.w;
    float m = fmaxf(fmaxf(fabsf(v.x), fabsf(v.y)), fmaxf(fabsf(v.z), fabsf(v.w)));
    #pragma unroll
    for (int o = 16; o > 0; o >>= 1) {
        s += __shfl_down_sync(0xFFFFFFFFu, s, o);
        m = fmaxf(m, __shfl_down_sync(0xFFFFFFFFu, m, o));
    }
    __shared__ float ws[8], wm[8];
    if ((threadIdx.x & 31) == 0) { ws[threadIdx.x >> 5] = s; wm[threadIdx.x >> 5] = m; }
    __syncthreads();
    if (threadIdx.x == 0) {
        float t = 0.f, mm = 0.f;
        #pragma unroll
        for (int i = 0; i < 8; i++) { t += ws[i]; mm = fmaxf(mm, wm[i]); }
        float iv = 1.0f / fmaxf(sqrtf(t), 1e-12f);
        inv[row] = iv;
        atomic_fmax(&g_amax[0], mm * sqrtf(iv));
        atomic_fmax(&g_amax[4], mm * iv);
    }
}

__global__ void amax_w(const float* __restrict__ w) {
    const int i = (blockIdx.x * 256 + threadIdx.x) * 4;
    float4 v = *reinterpret_cast<const float4*>(w + i);
    float m = fmaxf(fmaxf(fabsf(v.x), fabsf(v.y)), fmaxf(fabsf(v.z), fabsf(v.w)));
    #pragma unroll
    for (int o = 16; o > 0; o >>= 1) m = fmaxf(m, __shfl_down_sync(0xFFFFFFFFu, m, o));
    if ((threadIdx.x & 31) == 0) atomic_fmax(&g_amax[1], m);
}

__global__ void conv_x(const float* __restrict__ x, const float* __restrict__ inv,
                       s8* __restrict__ n1, s8* __restrict__ n2,
                       s8* __restrict__ y1, s8* __restrict__ y2) {
    __shared__ float sy[32][33];
    const float ky = 32000.0f / __uint_as_float(g_amax[0]);
    const float kn = 32000.0f / __uint_as_float(g_amax[4]);
    const int c = blockIdx.x * 32 + threadIdx.x;
    const int r0 = blockIdx.y * 32;
    #pragma unroll
    for (int i = 0; i < 4; i++) {
        int rl = threadIdx.y + i * 8;
        int r = r0 + rl;
        float iv = inv[r];
        float v = x[(size_t)r * DIM + c];
        s8 c1, c2;
        quant2(v * iv, kn, c1, c2);
        n1[(size_t)r * DIM + c] = c1;
        n2[(size_t)r * DIM + c] = c2;
        sy[rl][threadIdx.x] = v * sqrtf(iv);
    }
    __syncthreads();
    const int tr = r0 + threadIdx.x;
    #pragma unroll
    for (int i = 0; i < 4; i++) {
        int cl = threadIdx.y + i * 8;
        int tc = blockIdx.x * 32 + cl;
        s8 c1, c2;
        quant2(sy[threadIdx.x][cl], ky, c1, c2);
        y1[(size_t)tc * NROWS + tr] = c1;
        y2[(size_t)tc * NROWS + tr] = c2;
    }
}

__global__ void conv_w(const float* __restrict__ w,
                       s8* __restrict__ w1, s8* __restrict__ w2) {
    __shared__ float sw[32][33];
    const float kw = 32000.0f / __uint_as_float(g_amax[1]);
    const int c = blockIdx.x * 32 + threadIdx.x;
    const int r0 = blockIdx.y * 32;
    #pragma unroll
    for (int i = 0; i < 4; i++) {
        int rl = threadIdx.y + i * 8;
        sw[rl][threadIdx.x] = w[(size_t)(r0 + rl) * DIM + c];
    }
    __syncthreads();
    const int tr = r0 + threadIdx.x;
    #pragma unroll
    for (int i = 0; i < 4; i++) {
        int cl = threadIdx.y + i * 8;
        int tc = blockIdx.x * 32 + cl;
        s8 c1, c2;
        quant2(sw[threadIdx.x][cl], kw, c1, c2);
        w1[(size_t)tc * DIM + tr] = c1;
        w2[(size_t)tc * DIM + tr] = c2;
    }
}

// sum planes of a triangle block; extract+zero diagonal; mirror; amax(offdiag)
__global__ void combine_tri(const float* __restrict__ P, int np,
                            float* __restrict__ F, float* __restrict__ diag,
                            unsigned* __restrict__ amax) {
    const int2 bp = c_tri[blockIdx.y];
    const int idx = (blockIdx.x * 256 + threadIdx.x) * 4;
    const int R = bp.x * 128 + (idx >> 7);
    const int C = bp.y * 128 + (idx & 127);
    const size_t o = (size_t)R * DIM + C;
    float v[4] = {0.f, 0.f, 0.f, 0.f};
    for (int p = 0; p < np; p++) {
        float4 a = *reinterpret_cast<const float4*>(P + (size_t)p * DIM * DIM + o);
        v[0] += a.x; v[1] += a.y; v[2] += a.z; v[3] += a.w;
    }
    if (bp.x == bp.y) {
        #pragma unroll
        for (int j = 0; j < 4; j++)
            if (C + j == R) { diag[R] = v[j]; v[j] = 0.f; }
    }
    *reinterpret_cast<float4*>(F + o) = make_float4(v[0], v[1], v[2], v[3]);
    if (bp.x != bp.y) {
        #pragma unroll
        for (int j = 0; j < 4; j++) F[(size_t)(C + j) * DIM + R] = v[j];
    }
    float m = fmaxf(fmaxf(fabsf(v[0]), fabsf(v[1])), fmaxf(fabsf(v[2]), fabsf(v[3])));
    #pragma unroll
    for (int o2 = 16; o2 > 0; o2 >>= 1) m = fmaxf(m, __shfl_down_sync(0xFFFFFFFFu, m, o2));
    if ((threadIdx.x & 31) == 0) atomic_fmax(amax, m);
}

// sum planes (H^T layout [m,n]); add diag(G) correction: += diag[n]*W[n,m]; amax
__global__ void combine_hT(const float* __restrict__ P, int np,
                           const float* __restrict__ w, const float* __restrict__ diag,
                           float* __restrict__ F, unsigned* __restrict__ amax) {
    const int i = (blockIdx.x * 256 + threadIdx.x) * 4;
    const int m = i >> 10;
    const int n0 = i & 1023;
    float v[4] = {0.f, 0.f, 0.f, 0.f};
    for (int p = 0; p < np; p++) {
        float4 a = *reinterpret_cast<const float4*>(P + (size_t)p * DIM * DIM + i);
        v[0] += a.x; v[1] += a.y; v[2] += a.z; v[3] += a.w;
    }
    #pragma unroll
    for (int j = 0; j < 4; j++)
        v[j] = fmaf(diag[n0 + j], w[(size_t)(n0 + j) * DIM + m], v[j]);
    *reinterpret_cast<float4*>(F + i) = make_float4(v[0], v[1], v[2], v[3]);
    float m2 = fmaxf(fmaxf(fabsf(v[0]), fabsf(v[1])), fmaxf(fabsf(v[2]), fabsf(v[3])));
    #pragma unroll
    for (int o2 = 16; o2 > 0; o2 >>= 1) m2 = fmaxf(m2, __shfl_down_sync(0xFFFFFFFFu, m2, o2));
    if ((threadIdx.x & 31) == 0) atomic_fmax(amax, m2);
}

__global__ void quant_lin(const float* __restrict__ F, const unsigned* __restrict__ amax,
                          s8* __restrict__ c1o, s8* __restrict__ c2o) {
    const float k = 32000.0f / __uint_as_float(*amax);
    const int i = (blockIdx.x * 256 + threadIdx.x) * 4;
    float4 v = *reinterpret_cast<const float4*>(F + i);
    s8 a[4], b[4];
    quant2(v.x, k, a[0], b[0]); quant2(v.y, k, a[1], b[1]);
    quant2(v.z, k, a[2], b[2]); quant2(v.w, k, a[3], b[3]);
    *reinterpret_cast<uint32_t*>(c1o + i) = *reinterpret_cast<uint32_t*>(a);
    *reinterpret_cast<uint32_t*>(c2o + i) = *reinterpret_cast<uint32_t*>(b);
}

// ---------------- int8 IMMA GEMM: C[m,n] = sum_k A[m,k]*B[n,k] --------------
// CTA 128x128, BK=64, 8 warps (2m x 4n), warp tile 64x32, 3 s32 accumulators.
#define TILE_PB  10240
#define STAGE_B  (4 * TILE_PB)
#define SMEM_DYN (2 * STAGE_B)

__device__ __forceinline__ void stage_load(uint32_t s_stage,
                                           const s8* __restrict__ A1, const s8* __restrict__ A2,
                                           const s8* __restrict__ B1, const s8* __restrict__ B2,
                                           int m0, int n0, int k, int ldk, int tid) {
    #pragma unroll
    for (int j = 0; j < 2; j++) {
        const int idx = tid + j * 256;
        const int row = idx >> 2;
        const int cb = (idx & 3) * 16;
        const uint32_t so = s_stage + row * 80 + cb;
        const size_t goA = (size_t)(m0 + row) * ldk + k + cb;
        const size_t goB = (size_t)(n0 + row) * ldk + k + cb;
        CP16(so,               A1 + goA);
        CP16(so + TILE_PB,     A2 + goA);
        CP16(so + 2 * TILE_PB, B1 + goB);
        CP16(so + 3 * TILE_PB, B2 + goB);
    }
}

template <int TRI>
__global__ __launch_bounds__(256, 1)
void gemm_imma(const s8* __restrict__ A1, const s8* __restrict__ A2,
               const s8* __restrict__ B1, const s8* __restrict__ B2,
               float* __restrict__ Cbase, size_t cplane,
               const unsigned* __restrict__ pamaxA, const unsigned* __restrict__ pamaxB,
               int N, int ldk, int ksplit) {
    extern __shared__ char smem[];
    const uint32_t su = smem_u32(smem);
    const int tid = threadIdx.x;
    const int lane = tid & 31;
    const int wid = tid >> 5;
    const int warp_m = wid & 1;
    const int warp_n = wid >> 1;
    int m0, n0;
    if (TRI) {
        const int2 bp = c_tri[blockIdx.x];
        m0 = bp.x * 128; n0 = bp.y * 128;
    } else {
        m0 = blockIdx.y * 128; n0 = blockIdx.x * 128;
    }
    const int k0 = blockIdx.z * ksplit;
    float* C = Cbase + (size_t)blockIdx.z * cplane;

    int acc1[4][4][4], acc2[4][4][4], acc3[4][4][4];
    #pragma unroll
    for (int i = 0; i < 4; i++)
        #pragma unroll
        for (int j = 0; j < 4; j++)
            #pragma unroll
            for (int q = 0; q < 4; q++) { acc1[i][j][q] = 0; acc2[i][j][q] = 0; acc3[i][j][q] = 0; }

    const uint32_t a_off = (uint32_t)(warp_m * 64 + (lane & 15)) * 80 + ((lane >> 4) << 4);
    const uint32_t b_off = (uint32_t)(warp_n * 32 + ((lane >> 4) << 3) + (lane & 7)) * 80
                         + (((lane >> 3) & 1) << 4);

    const int NIT = ksplit / 64;
    stage_load(su, A1, A2, B1, B2, m0, n0, k0, ldk, tid);
    CP_COMMIT();

    for (int it = 0; it < NIT; it++) {
        if (it + 1 < NIT) {
            stage_load(su + ((it + 1) & 1) * STAGE_B, A1, A2, B1, B2,
                       m0, n0, k0 + (it + 1) * 64, ldk, tid);
            CP_COMMIT();
            CP_WAIT(1);
        } else {
            CP_WAIT(0);
        }
        __syncthreads();

        const uint32_t st = su + (it & 1) * STAGE_B;
        const uint32_t a1p = st + a_off;
        const uint32_t a2p = a1p + TILE_PB;
        const uint32_t b1p = st + 2 * TILE_PB + b_off;
        const uint32_t b2p = b1p + TILE_PB;

        #pragma unroll
        for (int ks = 0; ks < 2; ks++) {
            uint32_t af1[4][4], af2[4][4], bf1[4][2], bf2[4][2];
            #pragma unroll
            for (int mf = 0; mf < 4; mf++) {
                LDSM4(af1[mf], a1p + mf * 1280 + ks * 32);
                LDSM4(af2[mf], a2p + mf * 1280 + ks * 32);
            }
            #pragma unroll
            for (int bg = 0; bg < 2; bg++) {
                uint32_t t[4];
                LDSM4(t, b1p + bg * 1280 + ks * 32);
                bf1[2 * bg][0] = t[0]; bf1[2 * bg][1] = t[1];
                bf1[2 * bg + 1][0] = t[2]; bf1[2 * bg + 1][1] = t[3];
                LDSM4(t, b2p + bg * 1280 + ks * 32);
                bf2[2 * bg][0] = t[0]; bf2[2 * bg][1] = t[1];
                bf2[2 * bg + 1][0] = t[2]; bf2[2 * bg + 1][1] = t[3];
            }
            #pragma unroll
            for (int mf = 0; mf < 4; mf++)
                #pragma unroll
                for (int nf = 0; nf < 4; nf++) {
                    IMMA(acc1[mf][nf], af1[mf], bf1[nf]);   // P11
                    IMMA(acc2[mf][nf], af1[mf], bf2[nf]);   // P12
                    IMMA(acc2[mf][nf], af2[mf], bf1[nf]);   // P21
                    IMMA(acc3[mf][nf], af2[mf], bf2[nf]);   // P22
                }
        }
        __syncthreads();
    }

    const float sab = __uint_as_float(*pamaxA) * __uint_as_float(*pamaxB) * 9.765625e-10f;
    const int g = lane >> 2, t4 = lane & 3;
    #pragma unroll
    for (int mf = 0; mf < 4; mf++) {
        const int r = m0 + warp_m * 64 + mf * 16 + g;
        #pragma unroll
        for (int nf = 0; nf < 4; nf++) {
            const int c = n0 + warp_n * 32 + nf * 8 + t4 * 2;
            float v[4];
            #pragma unroll
            for (int q = 0; q < 4; q++)
                v[q] = sab * fmaf(64009.0f, (float)acc1[mf][nf][q],
                          fmaf(253.0f, (float)acc2[mf][nf][q], (float)acc3[mf][nf][q]));
            *reinterpret_cast<float2*>(C + (size_t)r * N + c) = make_float2(v[0], v[1]);
            *reinterpret_cast<float2*>(C + (size_t)(r + 8) * N + c) = make_float2(v[2], v[3]);
        }
    }
}

// ---------------------------------------------------------------------------
extern "C" void kernel_launch(void* const* d_in, const int* in_sizes, int n_in,
                              void* d_out, int out_size) {
    const float* x = (const float*)d_in[0];
    const float* w = (const float*)d_in[1];
    float* out = (float*)d_out;

    float *inv, *P, *Gf, *Hf, *diag;
    unsigned* amax;
    cudaGetSymbolAddress((void**)&inv, g_inv);
    cudaGetSymbolAddress((void**)&P, g_P);
    cudaGetSymbolAddress((void**)&Gf, g_Gf);
    cudaGetSymbolAddress((void**)&Hf, g_Hf);
    cudaGetSymbolAddress((void**)&diag, g_diag);
    cudaGetSymbolAddress((void**)&amax, g_amax);
    s8 *n1, *n2, *y1, *y2, *w1, *w2, *g1, *g2, *h1, *h2;
    cudaGetSymbolAddress((void**)&n1, q_n1); cudaGetSymbolAddress((void**)&n2, q_n2);
    cudaGetSymbolAddress((void**)&y1, q_y1); cudaGetSymbolAddress((void**)&y2, q_y2);
    cudaGetSymbolAddress((void**)&w1, q_w1); cudaGetSymbolAddress((void**)&w2, q_w2);
    cudaGetSymbolAddress((void**)&g1, q_g1); cudaGetSymbolAddress((void**)&g2, q_g2);
    cudaGetSymbolAddress((void**)&h1, q_h1); cudaGetSymbolAddress((void**)&h2, q_h2);

    cudaFuncSetAttribute(gemm_imma<0>, cudaFuncAttributeMaxDynamicSharedMemorySize, SMEM_DYN);
    cudaFuncSetAttribute(gemm_imma<1>, cudaFuncAttributeMaxDynamicSharedMemorySize, SMEM_DYN);

    init_amax<<<1, 32>>>();
    rownorm_inv<<<NROWS, 256>>>(x, inv);
    amax_w<<<DIM * DIM / 1024, 256>>>(w);
    conv_x<<<dim3(DIM / 32, NROWS / 32), dim3(32, 8)>>>(x, inv, n1, n2, y1, y2);
    conv_w<<<dim3(DIM / 32, DIM / 32), dim3(32, 8)>>>(w, w1, w2);

    // G = y^T @ y (symmetric): 36 triangle blocks, split-K=4 -> 144 CTAs
    gemm_imma<1><<<dim3(36, 1, 4), 256, SMEM_DYN>>>(
        y1, y2, y1, y2, P, (size_t)DIM * DIM, amax + 0, amax + 0, DIM, NROWS, NROWS / 4);
    combine_tri<<<dim3(16, 36), 256>>>(P, 4, Gf, diag, amax + 2);
    quant_lin<<<DIM * DIM / 1024, 256>>>(Gf, amax + 2, g1, g2);

    // H^T = MM(W^T, G_offdiag): split-K=2; then += diag(G)[n]*W[n,m] in fp32
    gemm_imma<0><<<dim3(8, 8, 2), 256, SMEM_DYN>>>(
        w1, w2, g1, g2, P, (size_t)DIM * DIM, amax + 1, amax + 2, DIM, DIM, DIM / 2);
    combine_hT<<<DIM * DIM / 1024, 256>>>(P, 2, w, diag, Hf, amax + 3);
    quant_lin<<<DIM * DIM / 1024, 256>>>(Hf, amax + 3, h1, h2);

    // out = MM(norm, H^T): 512 CTAs
    gemm_imma<0><<<dim3(8, 64, 1), 256, SMEM_DYN>>>(
        n1, n2, h1, h2, out, 0, amax + 4, amax + 3, DIM, DIM, DIM);
}

// round 10
// speedup vs baseline: 4.2283x; 4.2283x over previous
#include <cuda_runtime.h>
#include <cuda_fp16.h>
#include <cstdint>

// out = norm @ ((norm^T @ x) @ W),  norm = x / max(||x_row||, 1e-12)
// y = sqrt(inv)*x  =>  G = y^T @ y (symmetric).
// GEMMs: fp16 hi/lo split, TWO passes (C ~= ah*bh + ah*bl; dropped la*hb ~2^-12):
// mma.sync.m16n8k16.f32.f16.f16.f32. A side needs hi only.

#define NROWS 8192
#define DIM   1024
typedef __half f16;

// ---------------- scratch (device globals; no allocation allowed) ----------
__device__ float g_inv[NROWS];
__device__ f16 g_nh[NROWS * DIM];                       // norm hi, row-major
__device__ f16 g_yh[DIM * NROWS], g_yl[DIM * NROWS];    // y^T hi/lo [1024,8192]
__device__ f16 g_wh[DIM * DIM];                         // W^T hi
__device__ f16 g_gh[DIM * DIM],  g_gl[DIM * DIM];       // G hi/lo
__device__ f16 g_hh[DIM * DIM],  g_hl[DIM * DIM];       // H^T hi/lo
__device__ float g_P[8 * DIM * DIM];                    // split-K partials

__constant__ int2 c_tri[36] = {
    {0,0},{1,0},{1,1},{2,0},{2,1},{2,2},{3,0},{3,1},{3,2},{3,3},
    {4,0},{4,1},{4,2},{4,3},{4,4},{5,0},{5,1},{5,2},{5,3},{5,4},
    {5,5},{6,0},{6,1},{6,2},{6,3},{6,4},{6,5},{6,6},{7,0},{7,1},
    {7,2},{7,3},{7,4},{7,5},{7,6},{7,7}
};

// ---------------- PTX helpers ----------------------------------------------
__device__ __forceinline__ uint32_t smem_u32(const void* p) {
    uint32_t a;
    asm("{ .reg .u64 t; cvta.to.shared.u64 t, %1; cvt.u32.u64 %0, t; }" : "=r"(a) : "l"(p));
    return a;
}

#define CP16(saddr, gptr) \
    asm volatile("cp.async.cg.shared.global [%0], [%1], 16;" :: "r"(saddr), "l"(gptr))
#define CP_COMMIT() asm volatile("cp.async.commit_group;" ::: "memory")
#define CP_WAIT(n)  asm volatile("cp.async.wait_group %0;" :: "n"(n) : "memory")

#define LDSM4(r, addr) \
    asm volatile("ldmatrix.sync.aligned.m8n8.x4.shared.b16 {%0,%1,%2,%3}, [%4];" \
        : "=r"((r)[0]), "=r"((r)[1]), "=r"((r)[2]), "=r"((r)[3]) : "r"(addr))

#define MMA(c, a, b) \
    asm volatile("mma.sync.aligned.m16n8k16.row.col.f32.f16.f16.f32 " \
        "{%0,%1,%2,%3}, {%4,%5,%6,%7}, {%8,%9}, {%0,%1,%2,%3};" \
        : "+f"((c)[0]), "+f"((c)[1]), "+f"((c)[2]), "+f"((c)[3]) \
        : "r"((a)[0]), "r"((a)[1]), "r"((a)[2]), "r"((a)[3]), "r"((b)[0]), "r"((b)[1]))

// ---------------- small kernels --------------------------------------------
__global__ void rownorm_inv(const float* __restrict__ x, float* __restrict__ inv) {
    const int row = blockIdx.x;
    float4 v = reinterpret_cast<const float4*>(x + (size_t)row * DIM)[threadIdx.x];
    float s = v.x * v.x + v.y * v.y + v.z * v.z + v.w * v.w;
    #pragma unroll
    for (int o = 16; o > 0; o >>= 1) s += __shfl_down_sync(0xFFFFFFFFu, s, o);
    __shared__ float ws[8];
    if ((threadIdx.x & 31) == 0) ws[threadIdx.x >> 5] = s;
    __syncthreads();
    if (threadIdx.x == 0) {
        float t = 0.f;
        #pragma unroll
        for (int i = 0; i < 8; i++) t += ws[i];
        inv[row] = 1.0f / fmaxf(sqrtf(t), 1e-12f);
    }
}

__device__ __forceinline__ void split_h(float v, f16& h, f16& l) {
    h = __float2half_rn(v);
    l = __float2half_rn(v - __half2float(h));
}

// x -> norm hi (row-major), y^T hi/lo (K-major); y = sqrt(inv)*x
__global__ void conv_x(const float* __restrict__ x, const float* __restrict__ inv,
                       f16* __restrict__ nh,
                       f16* __restrict__ yh, f16* __restrict__ yl) {
    __shared__ float sy[32][33];
    const int c = blockIdx.x * 32 + threadIdx.x;
    const int r0 = blockIdx.y * 32;
    #pragma unroll
    for (int i = 0; i < 4; i++) {
        int rl = threadIdx.y + i * 8;
        int r = r0 + rl;
        float iv = inv[r];
        float v = x[(size_t)r * DIM + c];
        nh[(size_t)r * DIM + c] = __float2half_rn(v * iv);
        sy[rl][threadIdx.x] = v * sqrtf(iv);
    }
    __syncthreads();
    const int tr = r0 + threadIdx.x;
    #pragma unroll
    for (int i = 0; i < 4; i++) {
        int cl = threadIdx.y + i * 8;
        int tc = blockIdx.x * 32 + cl;
        f16 h, l;
        split_h(sy[threadIdx.x][cl], h, l);
        yh[(size_t)tc * NROWS + tr] = h;
        yl[(size_t)tc * NROWS + tr] = l;
    }
}

// W -> W^T hi
__global__ void conv_w(const float* __restrict__ w, f16* __restrict__ wh) {
    __shared__ float sw[32][33];
    const int c = blockIdx.x * 32 + threadIdx.x;
    const int r0 = blockIdx.y * 32;
    #pragma unroll
    for (int i = 0; i < 4; i++) {
        int rl = threadIdx.y + i * 8;
        sw[rl][threadIdx.x] = w[(size_t)(r0 + rl) * DIM + c];
    }
    __syncthreads();
    const int tr = r0 + threadIdx.x;
    #pragma unroll
    for (int i = 0; i < 4; i++) {
        int cl = threadIdx.y + i * 8;
        int tc = blockIdx.x * 32 + cl;
        wh[(size_t)tc * DIM + tr] = __float2half_rn(sw[threadIdx.x][cl]);
    }
}

// sum NP split-K partials of a triangle block, split fp16 hi/lo, mirror
__global__ void combine_tri(const float* __restrict__ P, int np,
                            f16* __restrict__ hi, f16* __restrict__ lo) {
    const int2 bp = c_tri[blockIdx.y];
    const int idx = (blockIdx.x * 256 + threadIdx.x) * 4;
    const int R = bp.x * 128 + (idx >> 7);
    const int C = bp.y * 128 + (idx & 127);
    const size_t o = (size_t)R * DIM + C;
    float v[4] = {0.f, 0.f, 0.f, 0.f};
    for (int p = 0; p < np; p++) {
        float4 a = *reinterpret_cast<const float4*>(P + (size_t)p * DIM * DIM + o);
        v[0] += a.x; v[1] += a.y; v[2] += a.z; v[3] += a.w;
    }
    f16 h[4], l[4];
    #pragma unroll
    for (int j = 0; j < 4; j++) split_h(v[j], h[j], l[j]);
    *reinterpret_cast<uint2*>(hi + o) = *reinterpret_cast<const uint2*>(h);
    *reinterpret_cast<uint2*>(lo + o) = *reinterpret_cast<const uint2*>(l);
    if (bp.x != bp.y) {
        #pragma unroll
        for (int j = 0; j < 4; j++) {
            hi[(size_t)(C + j) * DIM + R] = h[j];
            lo[(size_t)(C + j) * DIM + R] = l[j];
        }
    }
}

__global__ void combine_lin(const float* __restrict__ P, int np,
                            f16* __restrict__ hi, f16* __restrict__ lo) {
    const int i = (blockIdx.x * 256 + threadIdx.x) * 4;
    float v[4] = {0.f, 0.f, 0.f, 0.f};
    for (int p = 0; p < np; p++) {
        float4 a = *reinterpret_cast<const float4*>(P + (size_t)p * DIM * DIM + i);
        v[0] += a.x; v[1] += a.y; v[2] += a.z; v[3] += a.w;
    }
    f16 h[4], l[4];
    #pragma unroll
    for (int j = 0; j < 4; j++) split_h(v[j], h[j], l[j]);
    *reinterpret_cast<uint2*>(hi + i) = *reinterpret_cast<const uint2*>(h);
    *reinterpret_cast<uint2*>(lo + i) = *reinterpret_cast<const uint2*>(l);
}

// ---------------- fp16 HMMA GEMM: C[m,n] = sum_k A[m,k]*B[n,k] --------------
// CTA 128x128, BK=32, 4 warps (2m x 2n), warp tile 64x64, 2-pass hi/lo.
// SMEM per stage: Ah, Bh, Bl tiles of 128 rows x 32 f16, padded row = 80B.
#define TILE_PB  10240                // 128 * 80
#define STAGE_B  (3 * TILE_PB)        // 30720
#define SMEM_DYN (2 * STAGE_B)        // 61440

__device__ __forceinline__ void stage_load(uint32_t s_stage,
                                           const f16* __restrict__ Ah,
                                           const f16* __restrict__ Bh, const f16* __restrict__ Bl,
                                           int m0, int n0, int k, int ldk, int tid) {
    #pragma unroll
    for (int i = 0; i < 4; i++) {
        const int idx = tid + i * 128;        // 0..511
        const int row = idx >> 2;             // 0..127
        const int cb = (idx & 3) * 16;        // 0,16,32,48 bytes
        const uint32_t so = s_stage + row * 80 + cb;
        const size_t goA = ((size_t)(m0 + row) * ldk + k) * 2 + cb;
        const size_t goB = ((size_t)(n0 + row) * ldk + k) * 2 + cb;
        CP16(so,               (const char*)Ah + goA);
        CP16(so + TILE_PB,     (const char*)Bh + goB);
        CP16(so + 2 * TILE_PB, (const char*)Bl + goB);
    }
}

template <int TRI>
__global__ __launch_bounds__(128, 2)
void gemm_f16(const f16* __restrict__ Ah,
              const f16* __restrict__ Bh, const f16* __restrict__ Bl,
              float* __restrict__ Cbase, size_t cplane,
              int N, int ldk, int ksplit) {
    extern __shared__ char smem[];
    const uint32_t su = smem_u32(smem);
    const int tid = threadIdx.x;
    const int lane = tid & 31;
    const int wid = tid >> 5;
    const int warp_m = wid & 1;
    const int warp_n = wid >> 1;
    int m0, n0;
    if (TRI) {
        const int2 bp = c_tri[blockIdx.x];
        m0 = bp.x * 128; n0 = bp.y * 128;
    } else {
        m0 = blockIdx.y * 128; n0 = blockIdx.x * 128;
    }
    const int k0 = blockIdx.z * ksplit;
    float* C = Cbase + (size_t)blockIdx.z * cplane;

    float acc[4][8][4];
    #pragma unroll
    for (int i = 0; i < 4; i++)
        #pragma unroll
        for (int j = 0; j < 8; j++)
            #pragma unroll
            for (int q = 0; q < 4; q++) acc[i][j][q] = 0.f;

    const uint32_t a_off = (uint32_t)(warp_m * 64 + (lane & 15)) * 80 + ((lane >> 4) << 4);
    const uint32_t b_off = (uint32_t)(warp_n * 64 + ((lane >> 4) << 3) + (lane & 7)) * 80
                         + (((lane >> 3) & 1) << 4);

    const int NIT = ksplit / 32;
    stage_load(su, Ah, Bh, Bl, m0, n0, k0, ldk, tid);
    CP_COMMIT();

    for (int it = 0; it < NIT; it++) {
        if (it + 1 < NIT) {
            stage_load(su + ((it + 1) & 1) * STAGE_B, Ah, Bh, Bl,
                       m0, n0, k0 + (it + 1) * 32, ldk, tid);
            CP_COMMIT();
            CP_WAIT(1);
        } else {
            CP_WAIT(0);
        }
        __syncthreads();

        const uint32_t st = su + (it & 1) * STAGE_B;
        const uint32_t a_h = st + a_off;
        const uint32_t b_h = st + TILE_PB + b_off;
        const uint32_t b_l = b_h + TILE_PB;

        #pragma unroll
        for (int ks = 0; ks < 2; ks++) {
            uint32_t ah[4][4], bh[8][2], bl[8][2];
            #pragma unroll
            for (int mf = 0; mf < 4; mf++) LDSM4(ah[mf], a_h + mf * 1280 + ks * 32);
            #pragma unroll
            for (int bg = 0; bg < 4; bg++) {
                uint32_t t[4];
                LDSM4(t, b_h + bg * 1280 + ks * 32);
                bh[2 * bg][0] = t[0]; bh[2 * bg][1] = t[1];
                bh[2 * bg + 1][0] = t[2]; bh[2 * bg + 1][1] = t[3];
                LDSM4(t, b_l + bg * 1280 + ks * 32);
                bl[2 * bg][0] = t[0]; bl[2 * bg][1] = t[1];
                bl[2 * bg + 1][0] = t[2]; bl[2 * bg + 1][1] = t[3];
            }
            #pragma unroll
            for (int mf = 0; mf < 4; mf++)
                #pragma unroll
                for (int nf = 0; nf < 8; nf++) {
                    MMA(acc[mf][nf], ah[mf], bh[nf]);
                    MMA(acc[mf][nf], ah[mf], bl[nf]);
                }
        }
        __syncthreads();
    }

    const int g = lane >> 2, t4 = lane & 3;
    #pragma unroll
    for (int mf = 0; mf < 4; mf++) {
        const int r = m0 + warp_m * 64 + mf * 16 + g;
        #pragma unroll
        for (int nf = 0; nf < 8; nf++) {
            const int c = n0 + warp_n * 64 + nf * 8 + t4 * 2;
            float2 v0 = make_float2(acc[mf][nf][0], acc[mf][nf][1]);
            float2 v1 = make_float2(acc[mf][nf][2], acc[mf][nf][3]);
            *reinterpret_cast<float2*>(C + (size_t)r * N + c) = v0;
            *reinterpret_cast<float2*>(C + (size_t)(r + 8) * N + c) = v1;
        }
    }
}

// ---------------------------------------------------------------------------
extern "C" void kernel_launch(void* const* d_in, const int* in_sizes, int n_in,
                              void* d_out, int out_size) {
    const float* x = (const float*)d_in[0];
    const float* w = (const float*)d_in[1];
    float* out = (float*)d_out;

    float *inv, *P;
    cudaGetSymbolAddress((void**)&inv, g_inv);
    cudaGetSymbolAddress((void**)&P, g_P);
    f16 *nh, *yh, *yl, *wh, *gh, *gl, *hh, *hl;
    cudaGetSymbolAddress((void**)&nh, g_nh);
    cudaGetSymbolAddress((void**)&yh, g_yh); cudaGetSymbolAddress((void**)&yl, g_yl);
    cudaGetSymbolAddress((void**)&wh, g_wh);
    cudaGetSymbolAddress((void**)&gh, g_gh); cudaGetSymbolAddress((void**)&gl, g_gl);
    cudaGetSymbolAddress((void**)&hh, g_hh); cudaGetSymbolAddress((void**)&hl, g_hl);

    cudaFuncSetAttribute(gemm_f16<0>, cudaFuncAttributeMaxDynamicSharedMemorySize, SMEM_DYN);
    cudaFuncSetAttribute(gemm_f16<1>, cudaFuncAttributeMaxDynamicSharedMemorySize, SMEM_DYN);

    rownorm_inv<<<NROWS, 256>>>(x, inv);
    conv_x<<<dim3(DIM / 32, NROWS / 32), dim3(32, 8)>>>(x, inv, nh, yh, yl);
    conv_w<<<dim3(DIM / 32, DIM / 32), dim3(32, 8)>>>(w, wh);

    // G = y^T @ y (symmetric): A=y hi, B=y hi/lo. 36 tri blocks x split-K 8 = 288 CTAs
    gemm_f16<1><<<dim3(36, 1, 8), 128, SMEM_DYN>>>(
        yh, yh, yl, P, (size_t)DIM * DIM, DIM, NROWS, NROWS / 8);
    combine_tri<<<dim3(16, 36), 256>>>(P, 8, gh, gl);

    // H^T = MM(W^T hi, G hi/lo): split-K=4 -> 256 CTAs
    gemm_f16<0><<<dim3(8, 8, 4), 128, SMEM_DYN>>>(
        wh, gh, gl, P, (size_t)DIM * DIM, DIM, DIM, DIM / 4);
    combine_lin<<<DIM * DIM / 1024, 256>>>(P, 4, hh, hl);

    // out = MM(norm hi, H^T hi/lo): 512 CTAs
    gemm_f16<0><<<dim3(8, 64, 1), 128, SMEM_DYN>>>(
        nh, hh, hl, out, 0, DIM, DIM, DIM);
}